// round 15
// baseline (speedup 1.0000x reference)
#include <cuda_runtime.h>
#include <cuda_bf16.h>
#include <cuda_fp16.h>
#include <cstdint>

#define N_NODES  100000
#define N_EDGES  1600000
#define N_GRAPHS 64
#define IN_DIM   128
#define HID_DIM  256
#define OUT_DIM  256
#define D        256
#define SCAN_NB  98
#define POOL_CH  24
#define CHUNK0   25600
#define CHUNK1   (N_NODES - CHUNK0)

// ---------------- scratch (no allocs allowed) ----------------
__device__ int   g_cnt   [N_NODES];
__device__ float g_dinv  [N_NODES];
__device__ int   g_start [N_NODES + 1];
__device__ int   g_cursor[N_NODES];
__device__ int   g_srow  [N_EDGES];
__device__ int   g_bsum  [SCAN_NB];
__device__ int   g_boff  [SCAN_NB];
__device__ __nv_bfloat16 g_xs[(size_t)N_NODES * IN_DIM];
__device__ __half g_aggh [(size_t)N_NODES * IN_DIM];       // fp16 agg1 output
__device__ __half g_hh   [(size_t)N_NODES * D];            // fp16 layer-1 output
__device__ __half g_h2h  [(size_t)N_NODES * D];            // fp16 layer-2 pre-quant
__device__ signed char g_q8[(size_t)N_NODES * D];          // int8 quantized rows
__device__ float g_rsc   [N_NODES];                        // per-row scales
__device__ __half g_w1t  [D * IN_DIM];                     // W1^T fp16 [256][128]
__device__ __half g_w2t  [D * HID_DIM];                    // W2^T fp16 [256][256]

// ---------------- stream/event plumbing ----------------
static cudaStream_t g_s1 = 0;
static cudaEvent_t  g_evRoot = 0, g_evDinv = 0, g_evPre = 0, g_evPlace = 0, g_evJoin = 0;
static bool g_ok = false;

namespace {
struct SInit {
    SInit() {
        bool ok = (cudaStreamCreateWithFlags(&g_s1, cudaStreamNonBlocking) == cudaSuccess);
        ok = ok && (cudaEventCreateWithFlags(&g_evRoot,  cudaEventDisableTiming) == cudaSuccess);
        ok = ok && (cudaEventCreateWithFlags(&g_evDinv,  cudaEventDisableTiming) == cudaSuccess);
        ok = ok && (cudaEventCreateWithFlags(&g_evPre,   cudaEventDisableTiming) == cudaSuccess);
        ok = ok && (cudaEventCreateWithFlags(&g_evPlace, cudaEventDisableTiming) == cudaSuccess);
        ok = ok && (cudaEventCreateWithFlags(&g_evJoin,  cudaEventDisableTiming) == cudaSuccess);
        g_ok = ok;
    }
};
static SInit s_init;
}

// ---------------- degree / CSR build ----------------
__global__ void hist_kernel(const int* __restrict__ cols, int* cnt) {
    int e = blockIdx.x * blockDim.x + threadIdx.x;
    if (e < N_EDGES) atomicAdd(&cnt[cols[e]], 1);
}

__global__ __launch_bounds__(256)
void partial_sum_kernel(const int* __restrict__ cnt, int* __restrict__ bsum) {
    __shared__ int sh[256];
    int b = blockIdx.x, t = threadIdx.x;
    int base = b * 1024;
    int s = 0;
    #pragma unroll
    for (int j = 0; j < 4; j++) {
        int i = base + t + j * 256;
        if (i < N_NODES) s += cnt[i];
    }
    sh[t] = s;
    __syncthreads();
    for (int off = 128; off > 0; off >>= 1) {
        if (t < off) sh[t] += sh[t + off];
        __syncthreads();
    }
    if (t == 0) bsum[b] = sh[0];
}

__global__ __launch_bounds__(128)
void scan_bsum_kernel(const int* __restrict__ bsum, int* __restrict__ boff) {
    __shared__ int sh[128];
    int t = threadIdx.x;
    sh[t] = (t < SCAN_NB) ? bsum[t] : 0;
    __syncthreads();
    for (int off = 1; off < 128; off <<= 1) {
        int v = (t >= off) ? sh[t - off] : 0;
        __syncthreads();
        sh[t] += v;
        __syncthreads();
    }
    if (t < SCAN_NB) boff[t] = (t == 0) ? 0 : sh[t - 1];
}

// scan_final + dinv fused
__global__ __launch_bounds__(256)
void scan_final_kernel(const int* __restrict__ cnt, const int* __restrict__ boff,
                       int* __restrict__ start, int* __restrict__ cursor,
                       float* __restrict__ dinv) {
    __shared__ int sh[256];
    int b = blockIdx.x, t = threadIdx.x;
    int base = b * 1024 + t * 4;
    int c[4];
    int s = 0;
    #pragma unroll
    for (int j = 0; j < 4; j++) {
        int i = base + j;
        c[j] = (i < N_NODES) ? cnt[i] : 0;
        s += c[j];
    }
    sh[t] = s;
    __syncthreads();
    for (int off = 1; off < 256; off <<= 1) {
        int v = (t >= off) ? sh[t - off] : 0;
        __syncthreads();
        sh[t] += v;
        __syncthreads();
    }
    int pre = boff[b] + ((t == 0) ? 0 : sh[t - 1]);
    #pragma unroll
    for (int j = 0; j < 4; j++) {
        int i = base + j;
        if (i < N_NODES) {
            start[i]  = pre;
            cursor[i] = pre;
            dinv[i]   = rsqrtf((float)(c[j] + 1));
        }
        pre += c[j];
    }
    if (b == 0 && t == 0) start[N_NODES] = N_EDGES;
}

__global__ void place_kernel(const int* __restrict__ rows, const int* __restrict__ cols,
                             int* cursor, int* __restrict__ srow)
{
    int e = blockIdx.x * blockDim.x + threadIdx.x;
    if (e >= N_EDGES) return;
    int c = cols[e];
    int p = atomicAdd(&cursor[c], 1);
    srow[p] = rows[e];
}

// ---------------- W transpose to fp16 ----------------
__global__ void transpose_wh_kernel(const float* __restrict__ W, __half* __restrict__ Wt, int K) {
    __shared__ float t[32][33];
    int k0 = blockIdx.x * 32, n0 = blockIdx.y * 32;
    int tx = threadIdx.x, ty = threadIdx.y;   // 32 x 8
    #pragma unroll
    for (int j = 0; j < 32; j += 8)
        t[ty + j][tx] = W[(size_t)(k0 + ty + j) * D + n0 + tx];
    __syncthreads();
    #pragma unroll
    for (int j = 0; j < 32; j += 8)
        Wt[(size_t)(n0 + ty + j) * K + k0 + tx] = __float2half(t[tx][ty + j]);
}

// ---------------- xs = bf16(x * dinv[node]) ----------------
__global__ __launch_bounds__(256)
void scale_x_kernel(const float* __restrict__ x, const float* __restrict__ dinv,
                    __nv_bfloat16* __restrict__ xs)
{
    int idx = blockIdx.x * blockDim.x + threadIdx.x;
    if (idx >= N_NODES * (IN_DIM / 2)) return;
    int node = idx >> 6;
    float dc = dinv[node];
    float2 v = ((const float2*)x)[idx];
    __nv_bfloat162 p = __floats2bfloat162_rn(v.x * dc, v.y * dc);
    ((__nv_bfloat162*)xs)[idx] = p;
}

// ---------------- layer-1 aggregation -> fp16 output ----------------
__device__ __forceinline__ void bf16x4_add(uint2 v, float* a) {
    float2 f0 = __bfloat1622float2(*(__nv_bfloat162*)&v.x);
    float2 f1 = __bfloat1622float2(*(__nv_bfloat162*)&v.y);
    a[0] += f0.x; a[1] += f0.y; a[2] += f1.x; a[3] += f1.y;
}

__global__ __launch_bounds__(256)
void agg1_kernel(const __nv_bfloat16* __restrict__ xs, const int* __restrict__ srow,
                 const int* __restrict__ start, const float* __restrict__ dinv,
                 __half* __restrict__ out, int nbase, int ncount)
{
    int warp = (blockIdx.x * blockDim.x + threadIdx.x) >> 5;
    int lane = threadIdx.x & 31;
    if (warp >= ncount) return;
    int node = nbase + warp;
    int s = start[node], e = start[node + 1];

    float acc[4] = {0, 0, 0, 0};
    uint2 sv = ((const uint2*)(xs + (size_t)node * IN_DIM))[lane];
    bf16x4_add(sv, acc);

    int i = s;
    for (; i + 8 <= e; i += 8) {
        int r0 = srow[i],     r1 = srow[i + 1], r2 = srow[i + 2], r3 = srow[i + 3];
        int r4 = srow[i + 4], r5 = srow[i + 5], r6 = srow[i + 6], r7 = srow[i + 7];
        uint2 v0 = ((const uint2*)(xs + (size_t)r0 * IN_DIM))[lane];
        uint2 v1 = ((const uint2*)(xs + (size_t)r1 * IN_DIM))[lane];
        uint2 v2 = ((const uint2*)(xs + (size_t)r2 * IN_DIM))[lane];
        uint2 v3 = ((const uint2*)(xs + (size_t)r3 * IN_DIM))[lane];
        uint2 v4 = ((const uint2*)(xs + (size_t)r4 * IN_DIM))[lane];
        uint2 v5 = ((const uint2*)(xs + (size_t)r5 * IN_DIM))[lane];
        uint2 v6 = ((const uint2*)(xs + (size_t)r6 * IN_DIM))[lane];
        uint2 v7 = ((const uint2*)(xs + (size_t)r7 * IN_DIM))[lane];
        bf16x4_add(v0, acc); bf16x4_add(v1, acc);
        bf16x4_add(v2, acc); bf16x4_add(v3, acc);
        bf16x4_add(v4, acc); bf16x4_add(v5, acc);
        bf16x4_add(v6, acc); bf16x4_add(v7, acc);
    }
    for (; i + 2 <= e; i += 2) {
        int r0 = srow[i], r1 = srow[i + 1];
        uint2 v0 = ((const uint2*)(xs + (size_t)r0 * IN_DIM))[lane];
        uint2 v1 = ((const uint2*)(xs + (size_t)r1 * IN_DIM))[lane];
        bf16x4_add(v0, acc); bf16x4_add(v1, acc);
    }
    if (i < e) {
        int r = srow[i];
        uint2 v = ((const uint2*)(xs + (size_t)r * IN_DIM))[lane];
        bf16x4_add(v, acc);
    }

    float dc = dinv[node];
    __half2 p0 = __floats2half2_rn(acc[0] * dc, acc[1] * dc);
    __half2 p1 = __floats2half2_rn(acc[2] * dc, acc[3] * dc);
    uint2 o;
    o.x = *(unsigned*)&p0;
    o.y = *(unsigned*)&p1;
    ((uint2*)(out + (size_t)node * IN_DIM))[lane] = o;
}

// ---------------- per-row int8 quantization of h2 ----------------
// One warp per node: absmax over 256 fp16, q = round(v * 127/max), rsc = max/127.
__global__ __launch_bounds__(256)
void quant_kernel(const __half* __restrict__ h2, signed char* __restrict__ q,
                  float* __restrict__ rsc, int nbase, int ncount)
{
    int warp = (blockIdx.x * blockDim.x + threadIdx.x) >> 5;
    int lane = threadIdx.x & 31;
    if (warp >= ncount) return;
    int node = nbase + warp;

    uint4 v = ((const uint4*)(h2 + (size_t)node * D))[lane];
    __half2* hv = (__half2*)&v;
    float f[8];
    float2 t0 = __half22float2(hv[0]);
    float2 t1 = __half22float2(hv[1]);
    float2 t2 = __half22float2(hv[2]);
    float2 t3 = __half22float2(hv[3]);
    f[0] = t0.x; f[1] = t0.y; f[2] = t1.x; f[3] = t1.y;
    f[4] = t2.x; f[5] = t2.y; f[6] = t3.x; f[7] = t3.y;

    float m = 0.f;
    #pragma unroll
    for (int j = 0; j < 8; j++) m = fmaxf(m, fabsf(f[j]));
    #pragma unroll
    for (int off = 16; off > 0; off >>= 1)
        m = fmaxf(m, __shfl_xor_sync(0xFFFFFFFFu, m, off));

    float inv = (m > 0.f) ? (127.f / m) : 0.f;
    int qb[8];
    #pragma unroll
    for (int j = 0; j < 8; j++) qb[j] = __float2int_rn(f[j] * inv);
    uint2 o;
    o.x = (qb[0] & 0xFF) | ((qb[1] & 0xFF) << 8) | ((qb[2] & 0xFF) << 16) | ((qb[3] & 0xFF) << 24);
    o.y = (qb[4] & 0xFF) | ((qb[5] & 0xFF) << 8) | ((qb[6] & 0xFF) << 16) | ((qb[7] & 0xFF) << 24);
    ((uint2*)(q + (size_t)node * D))[lane] = o;
    if (lane == 0) rsc[node] = (m > 0.f) ? (m / 127.f) : 0.f;
}

// ---------------- fused layer-2 aggregation (int8 gather) + global mean pool ----------------
__device__ __forceinline__ void i8x8_fma(uint2 v, float s, float* a) {
    a[0] = fmaf(s, (float)(signed char)(v.x      ), a[0]);
    a[1] = fmaf(s, (float)(signed char)(v.x >>  8), a[1]);
    a[2] = fmaf(s, (float)(signed char)(v.x >> 16), a[2]);
    a[3] = fmaf(s, (float)(signed char)(v.x >> 24), a[3]);
    a[4] = fmaf(s, (float)(signed char)(v.y      ), a[4]);
    a[5] = fmaf(s, (float)(signed char)(v.y >>  8), a[5]);
    a[6] = fmaf(s, (float)(signed char)(v.y >> 16), a[6]);
    a[7] = fmaf(s, (float)(signed char)(v.y >> 24), a[7]);
}

__device__ __forceinline__ int lower_bound_i(const int* a, int n, int v) {
    int lo = 0, hi = n;
    while (lo < hi) {
        int mid = (lo + hi) >> 1;
        if (a[mid] < v) lo = mid + 1; else hi = mid;
    }
    return lo;
}

__global__ __launch_bounds__(256)
void aggpool2_kernel(const signed char* __restrict__ q8, const float* __restrict__ rsc,
                     const int* __restrict__ srow, const int* __restrict__ start,
                     const float* __restrict__ dinv, const float* __restrict__ bias,
                     const int* __restrict__ batch, float* __restrict__ out)
{
    int g  = blockIdx.x;
    int ch = blockIdx.y;
    int w    = threadIdx.x >> 5;
    int lane = threadIdx.x & 31;

    __shared__ int slo, shi;
    __shared__ float red[8 * 256];
    if (threadIdx.x == 0) slo = lower_bound_i(batch, N_NODES, g);
    if (threadIdx.x == 1) shi = lower_bound_i(batch, N_NODES, g + 1);
    __syncthreads();
    int lo = slo, hi = shi;
    int cnt = hi - lo;

    float pool[8] = {0, 0, 0, 0, 0, 0, 0, 0};
    if (cnt > 0) {
        float4 b_lo = ((const float4*)bias)[lane * 2];
        float4 b_hi = ((const float4*)bias)[lane * 2 + 1];
        for (int node = lo + ch * 8 + w; node < hi; node += POOL_CH * 8) {
            int s = start[node], e = start[node + 1];
            float acc[8] = {0, 0, 0, 0, 0, 0, 0, 0};
            uint2 sv = ((const uint2*)(q8 + (size_t)node * D))[lane];
            i8x8_fma(sv, rsc[node], acc);
            int i = s;
            for (; i + 4 <= e; i += 4) {
                int r0 = srow[i], r1 = srow[i + 1], r2 = srow[i + 2], r3 = srow[i + 3];
                uint2 v0 = ((const uint2*)(q8 + (size_t)r0 * D))[lane];
                uint2 v1 = ((const uint2*)(q8 + (size_t)r1 * D))[lane];
                uint2 v2 = ((const uint2*)(q8 + (size_t)r2 * D))[lane];
                uint2 v3 = ((const uint2*)(q8 + (size_t)r3 * D))[lane];
                float s0 = rsc[r0], s1 = rsc[r1], s2 = rsc[r2], s3 = rsc[r3];
                i8x8_fma(v0, s0, acc); i8x8_fma(v1, s1, acc);
                i8x8_fma(v2, s2, acc); i8x8_fma(v3, s3, acc);
            }
            for (; i < e; i++) {
                int r = srow[i];
                uint2 v = ((const uint2*)(q8 + (size_t)r * D))[lane];
                i8x8_fma(v, rsc[r], acc);
            }
            float dc = dinv[node];
            pool[0] += fmaxf(fmaf(acc[0], dc, b_lo.x), 0.f);
            pool[1] += fmaxf(fmaf(acc[1], dc, b_lo.y), 0.f);
            pool[2] += fmaxf(fmaf(acc[2], dc, b_lo.z), 0.f);
            pool[3] += fmaxf(fmaf(acc[3], dc, b_lo.w), 0.f);
            pool[4] += fmaxf(fmaf(acc[4], dc, b_hi.x), 0.f);
            pool[5] += fmaxf(fmaf(acc[5], dc, b_hi.y), 0.f);
            pool[6] += fmaxf(fmaf(acc[6], dc, b_hi.z), 0.f);
            pool[7] += fmaxf(fmaf(acc[7], dc, b_hi.w), 0.f);
        }
        float inv = 1.f / (float)cnt;
        #pragma unroll
        for (int j = 0; j < 8; j++) pool[j] *= inv;
    }

    #pragma unroll
    for (int j = 0; j < 8; j++) red[w * 256 + lane * 8 + j] = pool[j];
    __syncthreads();
    int t = threadIdx.x;
    float s = 0.f;
    #pragma unroll
    for (int wj = 0; wj < 8; wj++) s += red[wj * 256 + t];
    atomicAdd(&out[g * D + t], s);
}

// ---------------- fp16 GEMM, mma.m16n8k16, cp.async 2-stage ----------------
__device__ __forceinline__ void mma_f16(float* c, const unsigned* a, const unsigned* b) {
    asm volatile(
        "mma.sync.aligned.m16n8k16.row.col.f32.f16.f16.f32 "
        "{%0,%1,%2,%3}, {%4,%5,%6,%7}, {%8,%9}, {%0,%1,%2,%3};"
        : "+f"(c[0]), "+f"(c[1]), "+f"(c[2]), "+f"(c[3])
        : "r"(a[0]), "r"(a[1]), "r"(a[2]), "r"(a[3]), "r"(b[0]), "r"(b[1]));
}

__device__ __forceinline__ void cp16(unsigned smem_dst, const void* gsrc, bool valid) {
    int sz = valid ? 16 : 0;
    asm volatile("cp.async.ca.shared.global [%0], [%1], 16, %2;"
                 :: "r"(smem_dst), "l"(gsrc), "r"(sz));
}

__device__ __forceinline__ void store_pair(__half* out, size_t idx, float v0, float v1) {
    __half2 p = __floats2half2_rn(v0, v1);
    *(unsigned*)(out + idx) = *(unsigned*)&p;
}

#define GEMM_BM 128
#define GEMM_BN 128
#define GEMM_BK 32
#define GEMM_ROWH 40
#define GEMM_A_HALFS (GEMM_BM * GEMM_ROWH)
#define GEMM_B_HALFS (GEMM_BN * GEMM_ROWH)
#define GEMM_SMEM_BYTES ((2 * GEMM_A_HALFS + 2 * GEMM_B_HALFS) * 2)

template <int K, bool RELU, bool SCALE>
__global__ __launch_bounds__(256)
void gemm_f16_kernel(const __half* __restrict__ A, const __half* __restrict__ Wt,
                     const float* __restrict__ bias, const float* __restrict__ dinv,
                     __half* __restrict__ out, int m_base)
{
    extern __shared__ __half smh[];
    const int tid  = threadIdx.x;
    const int wid  = tid >> 5;
    const int lane = tid & 31;
    const int gid  = lane >> 2;
    const int tig  = lane & 3;
    const int wm   = (wid & 3) * 32;
    const int wn   = (wid >> 2) * 64;

    const int m0 = m_base + blockIdx.x * GEMM_BM;
    const int n0 = blockIdx.y * GEMM_BN;

    unsigned sbase = (unsigned)__cvta_generic_to_shared(smh);
    unsigned aBase = sbase;
    unsigned bBase = sbase + 2 * GEMM_A_HALFS * 2;

    const int ld_r   = tid >> 1;
    const int ld_seg = (tid & 1) * 32;

    auto load_stage = [&](int s, int k0) {
        bool valid = (m0 + ld_r) < N_NODES;
        const char* asrc = (const char*)(A + (size_t)(m0 + ld_r) * K + k0) + ld_seg;
        unsigned adst = aBase + (unsigned)(s * GEMM_A_HALFS * 2 + ld_r * (GEMM_ROWH * 2) + ld_seg);
        cp16(adst,      asrc,      valid);
        cp16(adst + 16, asrc + 16, valid);
        const char* bsrc = (const char*)(Wt + (size_t)(n0 + ld_r) * K + k0) + ld_seg;
        unsigned bdst = bBase + (unsigned)(s * GEMM_B_HALFS * 2 + ld_r * (GEMM_ROWH * 2) + ld_seg);
        cp16(bdst,      bsrc,      true);
        cp16(bdst + 16, bsrc + 16, true);
        asm volatile("cp.async.commit_group;");
    };

    float c[2][8][4];
    #pragma unroll
    for (int mt = 0; mt < 2; mt++)
        #pragma unroll
        for (int nt = 0; nt < 8; nt++)
            #pragma unroll
            for (int r = 0; r < 4; r++) c[mt][nt][r] = 0.f;

    load_stage(0, 0);

    int cur = 0;
    for (int k0 = 0; k0 < K; k0 += GEMM_BK) {
        asm volatile("cp.async.wait_group 0;");
        __syncthreads();

        if (k0 + GEMM_BK < K)
            load_stage(cur ^ 1, k0 + GEMM_BK);

        const __half* Ah = smh + cur * GEMM_A_HALFS;
        const __half* Bh = smh + 2 * GEMM_A_HALFS + cur * GEMM_B_HALFS;

        #pragma unroll
        for (int ks = 0; ks < 2; ks++) {
            int kk = ks * 16;
            unsigned a[2][4];
            #pragma unroll
            for (int mt = 0; mt < 2; mt++) {
                int row = wm + mt * 16;
                a[mt][0] = *(const unsigned*)&Ah[(row + gid    ) * GEMM_ROWH + kk + 2 * tig];
                a[mt][1] = *(const unsigned*)&Ah[(row + gid + 8) * GEMM_ROWH + kk + 2 * tig];
                a[mt][2] = *(const unsigned*)&Ah[(row + gid    ) * GEMM_ROWH + kk + 2 * tig + 8];
                a[mt][3] = *(const unsigned*)&Ah[(row + gid + 8) * GEMM_ROWH + kk + 2 * tig + 8];
            }
            unsigned b[8][2];
            #pragma unroll
            for (int nt = 0; nt < 8; nt++) {
                int col = wn + nt * 8 + gid;
                b[nt][0] = *(const unsigned*)&Bh[col * GEMM_ROWH + kk + 2 * tig];
                b[nt][1] = *(const unsigned*)&Bh[col * GEMM_ROWH + kk + 2 * tig + 8];
            }
            #pragma unroll
            for (int mt = 0; mt < 2; mt++)
                #pragma unroll
                for (int nt = 0; nt < 8; nt++)
                    mma_f16(c[mt][nt], a[mt], b[nt]);
        }
        __syncthreads();
        cur ^= 1;
    }

    #pragma unroll
    for (int mt = 0; mt < 2; mt++) {
        #pragma unroll
        for (int rh = 0; rh < 2; rh++) {
            int row = m0 + wm + mt * 16 + gid + rh * 8;
            if (row >= N_NODES) continue;
            float sc = SCALE ? dinv[row] : 1.f;
            #pragma unroll
            for (int nt = 0; nt < 8; nt++) {
                int col = n0 + wn + nt * 8 + 2 * tig;
                float v0 = c[mt][nt][rh * 2 + 0] * sc;
                float v1 = c[mt][nt][rh * 2 + 1] * sc;
                if (RELU) {
                    v0 = fmaxf(v0 + bias[col],     0.f);
                    v1 = fmaxf(v1 + bias[col + 1], 0.f);
                }
                store_pair(out, (size_t)row * D + col, v0, v1);
            }
        }
    }
}

// ---------------------------------------------------------------------------
extern "C" void kernel_launch(void* const* d_in, const int* in_sizes, int n_in,
                              void* d_out, int out_size)
{
    const float* x     = (const float*)d_in[0];
    const int*   eidx  = (const int*)  d_in[1];
    const int*   batch = (const int*)  d_in[2];
    const float* W1    = (const float*)d_in[3];
    const float* b1    = (const float*)d_in[4];
    const float* W2    = (const float*)d_in[5];
    const float* b2    = (const float*)d_in[6];
    float* out = (float*)d_out;

    const int* erow = eidx;
    const int* ecol = eidx + N_EDGES;

    int *cnt, *startp, *cursor, *srow, *bsum, *boff;
    float *dinv, *rsc;
    __half *aggh, *hh, *h2h, *w1t, *w2t;
    signed char *q8;
    __nv_bfloat16 *xs;
    cudaGetSymbolAddress((void**)&cnt,    g_cnt);
    cudaGetSymbolAddress((void**)&dinv,   g_dinv);
    cudaGetSymbolAddress((void**)&startp, g_start);
    cudaGetSymbolAddress((void**)&cursor, g_cursor);
    cudaGetSymbolAddress((void**)&srow,   g_srow);
    cudaGetSymbolAddress((void**)&bsum,   g_bsum);
    cudaGetSymbolAddress((void**)&boff,   g_boff);
    cudaGetSymbolAddress((void**)&xs,     g_xs);
    cudaGetSymbolAddress((void**)&aggh,   g_aggh);
    cudaGetSymbolAddress((void**)&hh,     g_hh);
    cudaGetSymbolAddress((void**)&h2h,    g_h2h);
    cudaGetSymbolAddress((void**)&q8,     g_q8);
    cudaGetSymbolAddress((void**)&rsc,    g_rsc);
    cudaGetSymbolAddress((void**)&w1t,    g_w1t);
    cudaGetSymbolAddress((void**)&w2t,    g_w2t);

    static bool attr_done = false;
    if (!attr_done) {
        cudaFuncSetAttribute(gemm_f16_kernel<IN_DIM, true, false>,
                             cudaFuncAttributeMaxDynamicSharedMemorySize, GEMM_SMEM_BYTES);
        cudaFuncSetAttribute(gemm_f16_kernel<HID_DIM, false, true>,
                             cudaFuncAttributeMaxDynamicSharedMemorySize, GEMM_SMEM_BYTES);
        attr_done = true;
    }

    cudaStream_t s1 = g_ok ? g_s1 : (cudaStream_t)0;
    // Launch order is a dependency-valid TOTAL order -> single-stream fallback correct.

    if (g_ok) { cudaEventRecord(g_evRoot, 0); cudaStreamWaitEvent(s1, g_evRoot, 0); }

    // s1: prep (hidden under CSR build)
    transpose_wh_kernel<<<dim3(IN_DIM / 32, D / 32), dim3(32, 8), 0, s1>>>(W1, w1t, IN_DIM);
    transpose_wh_kernel<<<dim3(HID_DIM / 32, D / 32), dim3(32, 8), 0, s1>>>(W2, w2t, HID_DIM);
    cudaMemsetAsync(out, 0, (size_t)N_GRAPHS * D * sizeof(float), s1);

    // s0: CSR head
    cudaMemsetAsync(cnt, 0, (size_t)N_NODES * sizeof(int), 0);
    hist_kernel       <<<(N_EDGES + 255) / 256, 256>>>(ecol, cnt);
    partial_sum_kernel<<<SCAN_NB, 256>>>(cnt, bsum);
    scan_bsum_kernel  <<<1, 128>>>(bsum, boff);
    scan_final_kernel <<<SCAN_NB, 256>>>(cnt, boff, startp, cursor, dinv);
    if (g_ok) { cudaEventRecord(g_evDinv, 0); cudaStreamWaitEvent(s1, g_evDinv, 0); }

    // s1: scale_x (needs dinv) overlaps place
    scale_x_kernel<<<(N_NODES * (IN_DIM / 2) + 255) / 256, 256, 0, s1>>>(x, dinv, xs);
    if (g_ok) cudaEventRecord(g_evPre, s1);

    // s0: place
    place_kernel<<<(N_EDGES + 255) / 256, 256>>>(erow, ecol, cursor, srow);
    if (g_ok) { cudaEventRecord(g_evPlace, 0); cudaStreamWaitEvent(s1, g_evPlace, 0); }
    if (g_ok) cudaStreamWaitEvent(0, g_evPre, 0);

    // chunk 0 (stream 0)
    agg1_kernel<<<(CHUNK0 * 32) / 256, 256>>>(xs, srow, startp, dinv, aggh, 0, CHUNK0);
    gemm_f16_kernel<IN_DIM, true, false>
        <<<dim3(CHUNK0 / 128, 2), 256, GEMM_SMEM_BYTES>>>(aggh, w1t, b1, dinv, hh, 0);
    gemm_f16_kernel<HID_DIM, false, true>
        <<<dim3(CHUNK0 / 128, 2), 256, GEMM_SMEM_BYTES>>>(hh, w2t, b2, dinv, h2h, 0);
    quant_kernel<<<(CHUNK0 * 32) / 256, 256>>>(h2h, q8, rsc, 0, CHUNK0);

    // chunk 1 (stream 1)
    agg1_kernel<<<(CHUNK1 * 32 + 255) / 256, 256, 0, s1>>>(xs, srow, startp, dinv, aggh,
                                                           CHUNK0, CHUNK1);
    gemm_f16_kernel<IN_DIM, true, false>
        <<<dim3((CHUNK1 + 127) / 128, 2), 256, GEMM_SMEM_BYTES, s1>>>(aggh, w1t, b1, dinv, hh, CHUNK0);
    gemm_f16_kernel<HID_DIM, false, true>
        <<<dim3((CHUNK1 + 127) / 128, 2), 256, GEMM_SMEM_BYTES, s1>>>(hh, w2t, b2, dinv, h2h, CHUNK0);
    quant_kernel<<<(CHUNK1 * 32 + 255) / 256, 256, 0, s1>>>(h2h, q8, rsc, CHUNK0, CHUNK1);
    if (g_ok) { cudaEventRecord(g_evJoin, s1); cudaStreamWaitEvent(0, g_evJoin, 0); }

    // fused aggregate + pool (int8 gather + per-row scales)
    aggpool2_kernel<<<dim3(N_GRAPHS, POOL_CH), 256>>>(q8, rsc, srow, startp, dinv, b2, batch, out);
}